// round 4
// baseline (speedup 1.0000x reference)
#include <cuda_runtime.h>

#define NODE_D 128
#define EDGE_D 16
#define HIDDEN 300
#define KCAT   (NODE_D + EDGE_D)   // 144
#define MAXN   50000
#define MAXE   800000

// ---------------- scratch (static device globals; no allocs allowed) --------
static __device__ float g_h0 [(size_t)MAXN * HIDDEN];   // 60 MB
static __device__ float g_agg[(size_t)MAXN * HIDDEN];   // 60 MB
static __device__ float g_inc[(size_t)MAXN * EDGE_D];
static __device__ int   g_deg[MAXN];
static __device__ int   g_off[MAXN + 1];
static __device__ int   g_cur[MAXN];
static __device__ int   g_csrc[MAXE];
static __device__ int   g_ceid[MAXE];
static __device__ float g_cw  [MAXE];

// ---------------- CSR build -------------------------------------------------
__global__ void zero_kernel(int n) {
    int i = blockIdx.x * blockDim.x + threadIdx.x;
    if (i < n) { g_deg[i] = 0; g_cur[i] = 0; }
}

__global__ void hist_kernel(const int* __restrict__ ei, int E) {
    int e = blockIdx.x * blockDim.x + threadIdx.x;
    if (e < E) atomicAdd(&g_deg[ei[E + e]], 1);
}

// single-block exclusive scan of g_deg -> g_off (n up to 50176 handled)
__global__ void scan_kernel(int n) {
    __shared__ int sums[1024];
    int t = threadIdx.x;
    int C = (n + 1023) >> 10;
    int base = t * C;
    int s = 0;
    for (int i = 0; i < C; i++) { int idx = base + i; if (idx < n) s += g_deg[idx]; }
    sums[t] = s;
    __syncthreads();
    for (int d = 1; d < 1024; d <<= 1) {
        int v = (t >= d) ? sums[t - d] : 0;
        __syncthreads();
        sums[t] += v;
        __syncthreads();
    }
    int running = sums[t] - s;   // exclusive prefix for this chunk
    for (int i = 0; i < C; i++) {
        int idx = base + i;
        if (idx < n) { g_off[idx] = running; running += g_deg[idx]; }
    }
    if (t == 1023) g_off[n] = sums[1023];
}

__global__ void fill_kernel(const int* __restrict__ ei,
                            const float* __restrict__ ew, int E) {
    int e = blockIdx.x * blockDim.x + threadIdx.x;
    if (e < E) {
        int d = ei[E + e];
        int p = atomicAdd(&g_cur[d], 1);
        int j = g_off[d] + p;
        g_csrc[j] = ei[e];
        g_ceid[j] = e;
        g_cw[j]   = ew[e];
    }
}

// ---------------- inc = segment_sum(w * edge_attr) at dst  (warp per node) --
__global__ void inc_kernel(const float* __restrict__ edge_attr, int n) {
    int w    = (blockIdx.x * blockDim.x + threadIdx.x) >> 5;
    int lane = threadIdx.x & 31;
    if (w >= n) return;
    int start = g_off[w], end = g_off[w + 1];
    if (lane < EDGE_D) {
        float acc = 0.f;
        for (int j = start; j < end; j++)
            acc += g_cw[j] * edge_attr[(size_t)g_ceid[j] * EDGE_D + lane];
        g_inc[(size_t)w * EDGE_D + lane] = acc;
    }
}

// ---------------- agg = scatter-mean(w * h0[src]) at dst (block per node) ---
__global__ __launch_bounds__(128) void agg_kernel(int n) {
    __shared__ int   s_src[128];
    __shared__ float s_w[128];
    int node = blockIdx.x;
    int tid  = threadIdx.x;
    int start = g_off[node];
    int deg   = g_off[node + 1] - start;
    float a0 = 0.f, a1 = 0.f, a2 = 0.f;
    int c0 = tid, c1 = tid + 128, c2 = tid + 256;
    for (int b = 0; b < deg; b += 128) {
        int m = min(128, deg - b);
        if (tid < m) {
            s_src[tid] = g_csrc[start + b + tid];
            s_w[tid]   = g_cw  [start + b + tid];
        }
        __syncthreads();
        for (int j = 0; j < m; j++) {
            const float* row = g_h0 + (size_t)s_src[j] * HIDDEN;
            float wv = s_w[j];
            a0 += wv * row[c0];
            a1 += wv * row[c1];
            if (c2 < HIDDEN) a2 += wv * row[c2];
        }
        __syncthreads();
    }
    float inv = 1.f / fmaxf((float)deg, 1.f);
    float* outp = g_agg + (size_t)node * HIDDEN;
    outp[c0] = a0 * inv;
    outp[c1] = a1 * inv;
    if (c2 < HIDDEN) outp[c2] = a2 * inv;
}

// ---------------- GEMM config: 128x64 block tile, 8x8 micro-tile, 128 thr ---
// gemm1: h0 = relu(concat(x, inc) @ W0 + b0)   (K = 144)
__global__ __launch_bounds__(128) void gemm1_kernel(
    const float* __restrict__ X, const float* __restrict__ W0,
    const float* __restrict__ b0, float* __restrict__ h0_copy, int M)
{
    const int K = KCAT, NC = HIDDEN;
    __shared__ float As[16][129];
    __shared__ float Bs[16][64];
    int tid = threadIdx.x;
    int tx = tid & 7, ty = tid >> 3;
    int rowBase = blockIdx.y * 128;
    int colBase = blockIdx.x * 64;
    float acc[8][8];
#pragma unroll
    for (int i = 0; i < 8; i++)
#pragma unroll
        for (int j = 0; j < 8; j++) acc[i][j] = 0.f;

    for (int k0 = 0; k0 < K; k0 += 16) {
#pragma unroll
        for (int it = 0; it < 4; it++) {
            int f4 = it * 128 + tid;
            int m  = f4 >> 2;
            int kq = (f4 & 3) << 2;
            int row = rowBase + m;
            float4 v = make_float4(0.f, 0.f, 0.f, 0.f);
            if (row < M) {
                int k = k0 + kq;
                if (k < NODE_D) v = *(const float4*)(X + (size_t)row * NODE_D + k);
                else            v = *(const float4*)(g_inc + (size_t)row * EDGE_D + (k - NODE_D));
            }
            As[kq][m] = v.x; As[kq + 1][m] = v.y; As[kq + 2][m] = v.z; As[kq + 3][m] = v.w;
        }
#pragma unroll
        for (int it = 0; it < 2; it++) {
            int f4 = it * 128 + tid;
            int kk = f4 >> 4;
            int c4 = (f4 & 15) << 2;
            int k = k0 + kk;
            int c = colBase + c4;
            float4 v = make_float4(0.f, 0.f, 0.f, 0.f);
            if (k < K) {
                if (c + 3 < NC) v = *(const float4*)(W0 + (size_t)k * NC + c);
                else {
                    float* pv = (float*)&v;
                    for (int q = 0; q < 4; q++)
                        if (c + q < NC) pv[q] = W0[(size_t)k * NC + c + q];
                }
            }
            *(float4*)&Bs[kk][c4] = v;
        }
        __syncthreads();
#pragma unroll
        for (int kk = 0; kk < 16; kk++) {
            float a[8], bb[8];
#pragma unroll
            for (int i = 0; i < 8; i++) a[i] = As[kk][ty * 8 + i];
            float4 bv0 = *(const float4*)&Bs[kk][tx * 8];
            float4 bv1 = *(const float4*)&Bs[kk][tx * 8 + 4];
            bb[0] = bv0.x; bb[1] = bv0.y; bb[2] = bv0.z; bb[3] = bv0.w;
            bb[4] = bv1.x; bb[5] = bv1.y; bb[6] = bv1.z; bb[7] = bv1.w;
#pragma unroll
            for (int i = 0; i < 8; i++)
#pragma unroll
                for (int j = 0; j < 8; j++) acc[i][j] += a[i] * bb[j];
        }
        __syncthreads();
    }
#pragma unroll
    for (int i = 0; i < 8; i++) {
        int r = rowBase + ty * 8 + i;
        if (r >= M) continue;
#pragma unroll
        for (int j4 = 0; j4 < 8; j4 += 4) {
            int c = colBase + tx * 8 + j4;
            if (c >= NC) continue;
            if (c + 3 < NC) {
                float4 o;
                o.x = fmaxf(acc[i][j4 + 0] + b0[c + 0], 0.f);
                o.y = fmaxf(acc[i][j4 + 1] + b0[c + 1], 0.f);
                o.z = fmaxf(acc[i][j4 + 2] + b0[c + 2], 0.f);
                o.w = fmaxf(acc[i][j4 + 3] + b0[c + 3], 0.f);
                *(float4*)(g_h0   + (size_t)r * NC + c) = o;
                *(float4*)(h0_copy + (size_t)r * NC + c) = o;
            } else {
                for (int q = 0; q < 4 && c + q < NC; q++) {
                    float o = fmaxf(acc[i][j4 + q] + b0[c + q], 0.f);
                    g_h0   [(size_t)r * NC + c + q] = o;
                    h0_copy[(size_t)r * NC + c + q] = o;
                }
            }
        }
    }
}

// gemm2: h = relu(h0 + agg @ W + b)   (K = 300)
__global__ __launch_bounds__(128) void gemm2_kernel(
    const float* __restrict__ W, const float* __restrict__ bias,
    float* __restrict__ out, int M)
{
    const int K = HIDDEN, NC = HIDDEN;
    __shared__ float As[16][129];
    __shared__ float Bs[16][64];
    int tid = threadIdx.x;
    int tx = tid & 7, ty = tid >> 3;
    int rowBase = blockIdx.y * 128;
    int colBase = blockIdx.x * 64;
    float acc[8][8];
#pragma unroll
    for (int i = 0; i < 8; i++)
#pragma unroll
        for (int j = 0; j < 8; j++) acc[i][j] = 0.f;

    for (int k0 = 0; k0 < K; k0 += 16) {
#pragma unroll
        for (int it = 0; it < 4; it++) {
            int f4 = it * 128 + tid;
            int m  = f4 >> 2;
            int kq = (f4 & 3) << 2;
            int row = rowBase + m;
            float4 v = make_float4(0.f, 0.f, 0.f, 0.f);
            if (row < M) {
                int k = k0 + kq;
                if (k + 3 < K) v = *(const float4*)(g_agg + (size_t)row * K + k);
                else {
                    float* pv = (float*)&v;
                    for (int q = 0; q < 4; q++)
                        if (k + q < K) pv[q] = g_agg[(size_t)row * K + k + q];
                }
            }
            As[kq][m] = v.x; As[kq + 1][m] = v.y; As[kq + 2][m] = v.z; As[kq + 3][m] = v.w;
        }
#pragma unroll
        for (int it = 0; it < 2; it++) {
            int f4 = it * 128 + tid;
            int kk = f4 >> 4;
            int c4 = (f4 & 15) << 2;
            int k = k0 + kk;
            int c = colBase + c4;
            float4 v = make_float4(0.f, 0.f, 0.f, 0.f);
            if (k < K) {
                if (c + 3 < NC) v = *(const float4*)(W + (size_t)k * NC + c);
                else {
                    float* pv = (float*)&v;
                    for (int q = 0; q < 4; q++)
                        if (c + q < NC) pv[q] = W[(size_t)k * NC + c + q];
                }
            }
            *(float4*)&Bs[kk][c4] = v;
        }
        __syncthreads();
#pragma unroll
        for (int kk = 0; kk < 16; kk++) {
            float a[8], bb[8];
#pragma unroll
            for (int i = 0; i < 8; i++) a[i] = As[kk][ty * 8 + i];
            float4 bv0 = *(const float4*)&Bs[kk][tx * 8];
            float4 bv1 = *(const float4*)&Bs[kk][tx * 8 + 4];
            bb[0] = bv0.x; bb[1] = bv0.y; bb[2] = bv0.z; bb[3] = bv0.w;
            bb[4] = bv1.x; bb[5] = bv1.y; bb[6] = bv1.z; bb[7] = bv1.w;
#pragma unroll
            for (int i = 0; i < 8; i++)
#pragma unroll
                for (int j = 0; j < 8; j++) acc[i][j] += a[i] * bb[j];
        }
        __syncthreads();
    }
#pragma unroll
    for (int i = 0; i < 8; i++) {
        int r = rowBase + ty * 8 + i;
        if (r >= M) continue;
#pragma unroll
        for (int j4 = 0; j4 < 8; j4 += 4) {
            int c = colBase + tx * 8 + j4;
            if (c >= NC) continue;
            if (c + 3 < NC) {
                float4 h0v = *(const float4*)(g_h0 + (size_t)r * NC + c);
                float4 o;
                o.x = fmaxf(acc[i][j4 + 0] + bias[c + 0] + h0v.x, 0.f);
                o.y = fmaxf(acc[i][j4 + 1] + bias[c + 1] + h0v.y, 0.f);
                o.z = fmaxf(acc[i][j4 + 2] + bias[c + 2] + h0v.z, 0.f);
                o.w = fmaxf(acc[i][j4 + 3] + bias[c + 3] + h0v.w, 0.f);
                *(float4*)(out + (size_t)r * NC + c) = o;
            } else {
                for (int q = 0; q < 4 && c + q < NC; q++) {
                    float o = fmaxf(acc[i][j4 + q] + bias[c + q] +
                                    g_h0[(size_t)r * NC + c + q], 0.f);
                    out[(size_t)r * NC + c + q] = o;
                }
            }
        }
    }
}

// ---------------- launch ----------------------------------------------------
extern "C" void kernel_launch(void* const* d_in, const int* in_sizes, int n_in,
                              void* d_out, int out_size) {
    const float* x           = (const float*)d_in[0];
    const float* edge_attr   = (const float*)d_in[1];
    const float* edge_weight = (const float*)d_in[2];
    const float* W0          = (const float*)d_in[4];
    const float* b0          = (const float*)d_in[5];
    const float* W           = (const float*)d_in[6];
    const float* bvec        = (const float*)d_in[7];
    const int*   ei          = (const int*)d_in[8];

    int N = in_sizes[0] / NODE_D;
    int E = in_sizes[2];

    float* out_h  = (float*)d_out;
    float* out_h0 = out_h + (size_t)N * HIDDEN;

    zero_kernel<<<(N + 255) / 256, 256>>>(N);
    hist_kernel<<<(E + 255) / 256, 256>>>(ei, E);
    scan_kernel<<<1, 1024>>>(N);
    fill_kernel<<<(E + 255) / 256, 256>>>(ei, edge_weight, E);
    inc_kernel<<<((size_t)N * 32 + 255) / 256, 256>>>(edge_attr, N);

    dim3 gg((HIDDEN + 63) / 64, (N + 127) / 128);
    gemm1_kernel<<<gg, 128>>>(x, W0, b0, out_h0, N);
    agg_kernel<<<N, 128>>>(N);
    gemm2_kernel<<<gg, 128>>>(W, bvec, out_h, N);
}

// round 9
// speedup vs baseline: 1.3875x; 1.3875x over previous
#include <cuda_runtime.h>
#include <cstdint>

#define NODE_D 128
#define EDGE_D 16
#define HIDDEN 300
#define KCAT   (NODE_D + EDGE_D)   // 144
#define MAXN   50000
#define MAXE   800000

// ---------------- scratch (static device globals; no allocs allowed) --------
static __device__ float g_h0 [(size_t)MAXN * HIDDEN];   // 60 MB
static __device__ float g_agg[(size_t)MAXN * HIDDEN];   // 60 MB
static __device__ float g_inc[(size_t)MAXN * EDGE_D];
static __device__ int   g_deg[MAXN];
static __device__ int   g_off[MAXN + 1];
static __device__ int   g_cur[MAXN];
static __device__ int   g_csrc[MAXE];
static __device__ int   g_ceid[MAXE];
static __device__ float g_cw  [MAXE];

// ---------------- CSR build -------------------------------------------------
__global__ void zero_kernel(int n) {
    int i = blockIdx.x * blockDim.x + threadIdx.x;
    if (i < n) { g_deg[i] = 0; g_cur[i] = 0; }
}

__global__ void hist_kernel(const int* __restrict__ ei, int E) {
    int e = blockIdx.x * blockDim.x + threadIdx.x;
    if (e < E) atomicAdd(&g_deg[ei[E + e]], 1);
}

// single-block exclusive scan of g_deg -> g_off
__global__ void scan_kernel(int n) {
    __shared__ int sums[1024];
    int t = threadIdx.x;
    int C = (n + 1023) >> 10;
    int base = t * C;
    int s = 0;
    for (int i = 0; i < C; i++) { int idx = base + i; if (idx < n) s += g_deg[idx]; }
    sums[t] = s;
    __syncthreads();
    for (int d = 1; d < 1024; d <<= 1) {
        int v = (t >= d) ? sums[t - d] : 0;
        __syncthreads();
        sums[t] += v;
        __syncthreads();
    }
    int running = sums[t] - s;
    for (int i = 0; i < C; i++) {
        int idx = base + i;
        if (idx < n) { g_off[idx] = running; running += g_deg[idx]; }
    }
    if (t == 1023) g_off[n] = sums[1023];
}

__global__ void fill_kernel(const int* __restrict__ ei,
                            const float* __restrict__ ew, int E) {
    int e = blockIdx.x * blockDim.x + threadIdx.x;
    if (e < E) {
        int d = ei[E + e];
        int p = atomicAdd(&g_cur[d], 1);
        int j = g_off[d] + p;
        g_csrc[j] = ei[e];
        g_ceid[j] = e;
        g_cw[j]   = ew[e];
    }
}

// ---------------- inc = segment_sum(w * edge_attr) at dst  (warp per node) --
__global__ void inc_kernel(const float* __restrict__ edge_attr, int n) {
    int w    = (blockIdx.x * blockDim.x + threadIdx.x) >> 5;
    int lane = threadIdx.x & 31;
    if (w >= n) return;
    int start = g_off[w], end = g_off[w + 1];
    if (lane < EDGE_D) {
        float acc = 0.f;
        for (int j = start; j < end; j++)
            acc += g_cw[j] * edge_attr[(size_t)g_ceid[j] * EDGE_D + lane];
        g_inc[(size_t)w * EDGE_D + lane] = acc;
    }
}

// ---------------- agg = scatter-mean(w * h0[src]) at dst (block per node) ---
__global__ __launch_bounds__(128) void agg_kernel(int n) {
    __shared__ int   s_src[128];
    __shared__ float s_w[128];
    int node = blockIdx.x;
    int tid  = threadIdx.x;
    int start = g_off[node];
    int deg   = g_off[node + 1] - start;
    float a0 = 0.f, a1 = 0.f, a2 = 0.f;
    int c0 = tid, c1 = tid + 128, c2 = tid + 256;
    for (int b = 0; b < deg; b += 128) {
        int m = min(128, deg - b);
        if (tid < m) {
            s_src[tid] = g_csrc[start + b + tid];
            s_w[tid]   = g_cw  [start + b + tid];
        }
        __syncthreads();
        for (int j = 0; j < m; j++) {
            const float* row = g_h0 + (size_t)s_src[j] * HIDDEN;
            float wv = s_w[j];
            a0 += wv * row[c0];
            a1 += wv * row[c1];
            if (c2 < HIDDEN) a2 += wv * row[c2];
        }
        __syncthreads();
    }
    float inv = 1.f / fmaxf((float)deg, 1.f);
    float* outp = g_agg + (size_t)node * HIDDEN;
    outp[c0] = a0 * inv;
    outp[c1] = a1 * inv;
    if (c2 < HIDDEN) outp[c2] = a2 * inv;
}

// ---------------- tf32 tensor-core GEMM -------------------------------------
__device__ __forceinline__ uint32_t f2tf(float x) {
    uint32_t r;
    asm("cvt.rna.tf32.f32 %0, %1;" : "=r"(r) : "f"(x));
    return r;
}

__device__ __forceinline__ void mma8(float* c, const uint32_t* a, const uint32_t* b) {
    asm volatile(
        "mma.sync.aligned.m16n8k8.row.col.f32.tf32.tf32.f32 "
        "{%0,%1,%2,%3}, {%4,%5,%6,%7}, {%8,%9}, {%0,%1,%2,%3};\n"
        : "+f"(c[0]), "+f"(c[1]), "+f"(c[2]), "+f"(c[3])
        : "r"(a[0]), "r"(a[1]), "r"(a[2]), "r"(a[3]),
          "r"(b[0]), "r"(b[1]));
}

// MODE 1: h0 = relu(concat(x,inc) @ W0 + b0)  -> g_h0 (direct symbol) + outp (dup)
// MODE 2: h  = relu(h0 + agg @ W + b)         -> outp
// Block: 128 rows x 64 cols. 4 warps (2x2), warp tile 64x32, BK=32.
// NOTE: device globals (g_h0/g_agg/g_inc) are referenced ONLY inside device
// code — passing them as host-side kernel args silently resolves to the host
// shadow symbol (ATS-writable on GB300!) and was the Round-7 failure.
template<int MODE>
__global__ __launch_bounds__(128) void mma_gemm(
    const float* __restrict__ X,       // MODE1: x, MODE2: unused
    const float* __restrict__ Wg,      // [K][HIDDEN]
    const float* __restrict__ bias,
    float* __restrict__ outp,
    int M, int K)
{
    // A: k within each 8-group permuted so (k, k+4) are adjacent -> uint2 LDS
    __shared__ uint32_t As[128][36];   // stride 36 (pad 4): <=2-way conflicts
    __shared__ uint32_t Bs[64][33];    // natural k order, stride 33

    int tid  = threadIdx.x;
    int warp = tid >> 5, lane = tid & 31;
    int gid  = lane >> 2, tig = lane & 3;
    int wm   = (warp >> 1) * 64;
    int wn   = (warp & 1) * 32;
    int rowBase = blockIdx.y * 128;
    int colBase = blockIdx.x * 64;

    float acc[4][4][4];
#pragma unroll
    for (int mi = 0; mi < 4; mi++)
#pragma unroll
        for (int ni = 0; ni < 4; ni++)
#pragma unroll
            for (int q = 0; q < 4; q++) acc[mi][ni][q] = 0.f;

    for (int k0 = 0; k0 < K; k0 += 32) {
        // ---- A tile: 128x32, float4 global, permuted scatter to smem ----
#pragma unroll
        for (int it = 0; it < 8; it++) {
            int f4 = it * 128 + tid;
            int m  = f4 >> 3;
            int kq = (f4 & 7) << 2;
            int row = rowBase + m;
            int k = k0 + kq;
            float4 v = make_float4(0.f, 0.f, 0.f, 0.f);
            if (row < M) {
                if (MODE == 1) {
                    if (k < NODE_D)
                        v = *(const float4*)(X + (size_t)row * NODE_D + k);
                    else if (k < KCAT)
                        v = *(const float4*)(g_inc + (size_t)row * EDGE_D + (k - NODE_D));
                } else {
                    if (k < HIDDEN)
                        v = *(const float4*)(g_agg + (size_t)row * HIDDEN + k);
                }
            }
            const float* pv = (const float*)&v;
#pragma unroll
            for (int j = 0; j < 4; j++) {
                int kl = kq + j;
                int ph = (kl & ~7) | ((kl & 3) << 1) | ((kl >> 2) & 1);
                As[m][ph] = f2tf(pv[j]);
            }
        }
        // ---- B tile: 32x64 from Wg[k][c], transpose into Bs[n][k] ----
#pragma unroll
        for (int it = 0; it < 4; it++) {
            int f4 = it * 128 + tid;
            int kk = f4 >> 4;
            int c4 = (f4 & 15) << 2;
            int k = k0 + kk;
            int c = colBase + c4;
            float4 v = make_float4(0.f, 0.f, 0.f, 0.f);
            if (k < K && c < HIDDEN)
                v = *(const float4*)(Wg + (size_t)k * HIDDEN + c);
            const float* pv = (const float*)&v;
#pragma unroll
            for (int j = 0; j < 4; j++)
                Bs[c4 + j][kk] = f2tf(pv[j]);
        }
        __syncthreads();

#pragma unroll
        for (int ks = 0; ks < 4; ks++) {
            uint32_t a[4][4], b[4][2];
#pragma unroll
            for (int mi = 0; mi < 4; mi++) {
                int r0 = wm + mi * 16 + gid;
                uint2 lo = *(const uint2*)&As[r0][ks * 8 + 2 * tig];
                uint2 hi = *(const uint2*)&As[r0 + 8][ks * 8 + 2 * tig];
                a[mi][0] = lo.x;  // (gid,   k=tig)
                a[mi][1] = hi.x;  // (gid+8, k=tig)
                a[mi][2] = lo.y;  // (gid,   k=tig+4)
                a[mi][3] = hi.y;  // (gid+8, k=tig+4)
            }
#pragma unroll
            for (int ni = 0; ni < 4; ni++) {
                int n = wn + ni * 8 + gid;
                b[ni][0] = Bs[n][ks * 8 + tig];
                b[ni][1] = Bs[n][ks * 8 + tig + 4];
            }
#pragma unroll
            for (int mi = 0; mi < 4; mi++)
#pragma unroll
                for (int ni = 0; ni < 4; ni++)
                    mma8(acc[mi][ni], a[mi], b[ni]);
        }
        __syncthreads();
    }

    // ---- epilogue: c0=(gid,2t) c1=(gid,2t+1) c2=(gid+8,2t) c3=(gid+8,2t+1)
#pragma unroll
    for (int mi = 0; mi < 4; mi++) {
#pragma unroll
        for (int rr = 0; rr < 2; rr++) {
            int r = rowBase + wm + mi * 16 + gid + rr * 8;
            if (r >= M) continue;
#pragma unroll
            for (int ni = 0; ni < 4; ni++) {
                int c = colBase + wn + ni * 8 + 2 * tig;
                if (c >= HIDDEN) continue;   // c even, HIDDEN even -> c+1 ok
                float v0 = acc[mi][ni][rr * 2 + 0] + bias[c];
                float v1 = acc[mi][ni][rr * 2 + 1] + bias[c + 1];
                if (MODE == 2) {
                    const float* h0r = g_h0 + (size_t)r * HIDDEN + c;
                    v0 += h0r[0];
                    v1 += h0r[1];
                }
                v0 = fmaxf(v0, 0.f);
                v1 = fmaxf(v1, 0.f);
                float2 o = make_float2(v0, v1);
                *(float2*)(outp + (size_t)r * HIDDEN + c) = o;
                if (MODE == 1)   // internal copy via DEVICE symbol reference
                    *(float2*)(g_h0 + (size_t)r * HIDDEN + c) = o;
            }
        }
    }
}

// ---------------- launch ----------------------------------------------------
extern "C" void kernel_launch(void* const* d_in, const int* in_sizes, int n_in,
                              void* d_out, int out_size) {
    const float* x           = (const float*)d_in[0];
    const float* edge_attr   = (const float*)d_in[1];
    const float* edge_weight = (const float*)d_in[2];
    const float* W0          = (const float*)d_in[4];
    const float* b0          = (const float*)d_in[5];
    const float* W           = (const float*)d_in[6];
    const float* bvec        = (const float*)d_in[7];
    const int*   ei          = (const int*)d_in[8];

    int N = in_sizes[0] / NODE_D;
    int E = in_sizes[2];

    float* out_h  = (float*)d_out;
    float* out_h0 = out_h + (size_t)N * HIDDEN;

    zero_kernel<<<(N + 255) / 256, 256>>>(N);
    hist_kernel<<<(E + 255) / 256, 256>>>(ei, E);
    scan_kernel<<<1, 1024>>>(N);
    fill_kernel<<<(E + 255) / 256, 256>>>(ei, edge_weight, E);
    inc_kernel<<<((size_t)N * 32 + 255) / 256, 256>>>(edge_attr, N);

    dim3 gg((HIDDEN + 63) / 64, (N + 127) / 128);
    // gemm1: writes out_h0 (harness buffer) + g_h0 (device symbol, in-kernel)
    mma_gemm<1><<<gg, 128>>>(x, W0, b0, out_h0, N, KCAT);
    agg_kernel<<<N, 128>>>(N);
    // gemm2: h = relu(h0 + agg @ W + b)
    mma_gemm<2><<<gg, 128>>>(nullptr, W, bvec, out_h, N, HIDDEN);
}

// round 12
// speedup vs baseline: 1.5006x; 1.0815x over previous
#include <cuda_runtime.h>
#include <cstdint>

#define NODE_D 128
#define EDGE_D 16
#define HIDDEN 300
#define KCAT   (NODE_D + EDGE_D)   // 144
#define MAXN   50000
#define MAXE   800000

// ---------------- scratch (static device globals; no allocs allowed) --------
// NOTE: device globals are referenced ONLY inside device code — passing them
// as host-side kernel args resolves to the host shadow symbol (ATS-writable
// on GB300!) and silently corrupts (Round-7 failure).
static __device__ float g_agg[(size_t)MAXN * HIDDEN];   // 60 MB
static __device__ float g_inc[(size_t)MAXN * EDGE_D];
static __device__ int   g_deg[MAXN];
static __device__ int   g_off[MAXN + 1];
static __device__ int   g_cur[MAXN];
static __device__ int   g_csrc[MAXE];
static __device__ int   g_ceid[MAXE];
static __device__ float g_cw  [MAXE];

// ---------------- CSR build -------------------------------------------------
__global__ void zero_kernel(int n) {
    int i = blockIdx.x * blockDim.x + threadIdx.x;
    if (i < n) { g_deg[i] = 0; g_cur[i] = 0; }
}

__global__ void hist_kernel(const int* __restrict__ ei, int E) {
    int e = blockIdx.x * blockDim.x + threadIdx.x;
    if (e < E) atomicAdd(&g_deg[ei[E + e]], 1);
}

// single-block exclusive scan of g_deg -> g_off
__global__ void scan_kernel(int n) {
    __shared__ int sums[1024];
    int t = threadIdx.x;
    int C = (n + 1023) >> 10;
    int base = t * C;
    int s = 0;
    for (int i = 0; i < C; i++) { int idx = base + i; if (idx < n) s += g_deg[idx]; }
    sums[t] = s;
    __syncthreads();
    for (int d = 1; d < 1024; d <<= 1) {
        int v = (t >= d) ? sums[t - d] : 0;
        __syncthreads();
        sums[t] += v;
        __syncthreads();
    }
    int running = sums[t] - s;
    for (int i = 0; i < C; i++) {
        int idx = base + i;
        if (idx < n) { g_off[idx] = running; running += g_deg[idx]; }
    }
    if (t == 1023) g_off[n] = sums[1023];
}

__global__ void fill_kernel(const int* __restrict__ ei,
                            const float* __restrict__ ew, int E) {
    int e = blockIdx.x * blockDim.x + threadIdx.x;
    if (e < E) {
        int d = ei[E + e];
        int p = atomicAdd(&g_cur[d], 1);
        int j = g_off[d] + p;
        g_csrc[j] = ei[e];
        g_ceid[j] = e;
        g_cw[j]   = ew[e];
    }
}

// ---------------- inc = segment_sum(w * edge_attr) at dst  (warp per node) --
__global__ void inc_kernel(const float* __restrict__ edge_attr, int n) {
    int w    = (blockIdx.x * blockDim.x + threadIdx.x) >> 5;
    int lane = threadIdx.x & 31;
    if (w >= n) return;
    int start = g_off[w], end = g_off[w + 1];
    if (lane < EDGE_D) {
        float acc = 0.f;
        for (int j = start; j < end; j++)
            acc += g_cw[j] * edge_attr[(size_t)g_ceid[j] * EDGE_D + lane];
        g_inc[(size_t)w * EDGE_D + lane] = acc;
    }
}

// ---------------- agg = scatter-mean(w * h0[src]) at dst --------------------
// Warp per node, float4 lanes: lane covers float4 cols {lane, lane+32, lane+64}
// (75 float4 = 300 floats). csr entries read as uniform-address LDG (broadcast).
__global__ __launch_bounds__(256) void agg_kernel(const float* __restrict__ h0,
                                                  int n) {
    int w    = (blockIdx.x * blockDim.x + threadIdx.x) >> 5;
    int lane = threadIdx.x & 31;
    if (w >= n) return;
    int start = g_off[w], end = g_off[w + 1];
    int deg   = end - start;

    float4 a0 = make_float4(0.f, 0.f, 0.f, 0.f);
    float4 a1 = make_float4(0.f, 0.f, 0.f, 0.f);
    float4 a2 = make_float4(0.f, 0.f, 0.f, 0.f);
    bool tail = (lane < 11);   // 64 + lane <= 74 < 75

#pragma unroll 2
    for (int j = start; j < end; j++) {
        int   src = __ldg(&g_csrc[j]);
        float wv  = __ldg(&g_cw[j]);
        const float4* row = (const float4*)(h0 + (size_t)src * HIDDEN);
        float4 r0 = __ldg(&row[lane]);
        float4 r1 = __ldg(&row[lane + 32]);
        a0.x += wv * r0.x; a0.y += wv * r0.y; a0.z += wv * r0.z; a0.w += wv * r0.w;
        a1.x += wv * r1.x; a1.y += wv * r1.y; a1.z += wv * r1.z; a1.w += wv * r1.w;
        if (tail) {
            float4 r2 = __ldg(&row[lane + 64]);
            a2.x += wv * r2.x; a2.y += wv * r2.y; a2.z += wv * r2.z; a2.w += wv * r2.w;
        }
    }
    float inv = 1.f / fmaxf((float)deg, 1.f);
    float4* o = (float4*)(g_agg + (size_t)w * HIDDEN);
    o[lane]      = make_float4(a0.x * inv, a0.y * inv, a0.z * inv, a0.w * inv);
    o[lane + 32] = make_float4(a1.x * inv, a1.y * inv, a1.z * inv, a1.w * inv);
    if (tail)
        o[lane + 64] = make_float4(a2.x * inv, a2.y * inv, a2.z * inv, a2.w * inv);
}

// ---------------- tf32 tensor-core GEMM -------------------------------------
__device__ __forceinline__ uint32_t f2tf(float x) {
    uint32_t r;
    asm("cvt.rna.tf32.f32 %0, %1;" : "=r"(r) : "f"(x));
    return r;
}

__device__ __forceinline__ void mma8(float* c, const uint32_t* a, const uint32_t* b) {
    asm volatile(
        "mma.sync.aligned.m16n8k8.row.col.f32.tf32.tf32.f32 "
        "{%0,%1,%2,%3}, {%4,%5,%6,%7}, {%8,%9}, {%0,%1,%2,%3};\n"
        : "+f"(c[0]), "+f"(c[1]), "+f"(c[2]), "+f"(c[3])
        : "r"(a[0]), "r"(a[1]), "r"(a[2]), "r"(a[3]),
          "r"(b[0]), "r"(b[1]));
}

// MODE 1: h0 = relu(concat(x,inc) @ W0 + b0)  -> outp   (X = node attrs)
// MODE 2: h  = relu(X + agg @ W + b)          -> outp   (X = h0 buffer, residual)
// Block: 128 rows x 64 cols. 4 warps (2x2), warp tile 64x32, BK=32.
template<int MODE>
__global__ __launch_bounds__(128) void mma_gemm(
    const float* __restrict__ X,
    const float* __restrict__ Wg,      // [K][HIDDEN]
    const float* __restrict__ bias,
    float* __restrict__ outp,
    int M, int K)
{
    // A: k within each 8-group permuted so (k, k+4) are adjacent -> uint2 LDS
    __shared__ uint32_t As[128][36];   // stride 36 (pad 4): <=2-way conflicts
    __shared__ uint32_t Bs[64][33];    // natural k order, stride 33

    int tid  = threadIdx.x;
    int warp = tid >> 5, lane = tid & 31;
    int gid  = lane >> 2, tig = lane & 3;
    int wm   = (warp >> 1) * 64;
    int wn   = (warp & 1) * 32;
    int rowBase = blockIdx.y * 128;
    int colBase = blockIdx.x * 64;

    float acc[4][4][4];
#pragma unroll
    for (int mi = 0; mi < 4; mi++)
#pragma unroll
        for (int ni = 0; ni < 4; ni++)
#pragma unroll
            for (int q = 0; q < 4; q++) acc[mi][ni][q] = 0.f;

    for (int k0 = 0; k0 < K; k0 += 32) {
        // ---- A tile: 128x32, float4 global, permuted scatter to smem ----
#pragma unroll
        for (int it = 0; it < 8; it++) {
            int f4 = it * 128 + tid;
            int m  = f4 >> 3;
            int kq = (f4 & 7) << 2;
            int row = rowBase + m;
            int k = k0 + kq;
            float4 v = make_float4(0.f, 0.f, 0.f, 0.f);
            if (row < M) {
                if (MODE == 1) {
                    if (k < NODE_D)
                        v = *(const float4*)(X + (size_t)row * NODE_D + k);
                    else if (k < KCAT)
                        v = *(const float4*)(g_inc + (size_t)row * EDGE_D + (k - NODE_D));
                } else {
                    if (k < HIDDEN)
                        v = *(const float4*)(g_agg + (size_t)row * HIDDEN + k);
                }
            }
            const float* pv = (const float*)&v;
#pragma unroll
            for (int j = 0; j < 4; j++) {
                int kl = kq + j;
                int ph = (kl & ~7) | ((kl & 3) << 1) | ((kl >> 2) & 1);
                As[m][ph] = f2tf(pv[j]);
            }
        }
        // ---- B tile: 32x64 from Wg[k][c], transpose into Bs[n][k] ----
#pragma unroll
        for (int it = 0; it < 4; it++) {
            int f4 = it * 128 + tid;
            int kk = f4 >> 4;
            int c4 = (f4 & 15) << 2;
            int k = k0 + kk;
            int c = colBase + c4;
            float4 v = make_float4(0.f, 0.f, 0.f, 0.f);
            if (k < K && c < HIDDEN)
                v = *(const float4*)(Wg + (size_t)k * HIDDEN + c);
            const float* pv = (const float*)&v;
#pragma unroll
            for (int j = 0; j < 4; j++)
                Bs[c4 + j][kk] = f2tf(pv[j]);
        }
        __syncthreads();

#pragma unroll
        for (int ks = 0; ks < 4; ks++) {
            uint32_t a[4][4], b[4][2];
#pragma unroll
            for (int mi = 0; mi < 4; mi++) {
                int r0 = wm + mi * 16 + gid;
                uint2 lo = *(const uint2*)&As[r0][ks * 8 + 2 * tig];
                uint2 hi = *(const uint2*)&As[r0 + 8][ks * 8 + 2 * tig];
                a[mi][0] = lo.x;  // (gid,   k=tig)
                a[mi][1] = hi.x;  // (gid+8, k=tig)
                a[mi][2] = lo.y;  // (gid,   k=tig+4)
                a[mi][3] = hi.y;  // (gid+8, k=tig+4)
            }
#pragma unroll
            for (int ni = 0; ni < 4; ni++) {
                int n = wn + ni * 8 + gid;
                b[ni][0] = Bs[n][ks * 8 + tig];
                b[ni][1] = Bs[n][ks * 8 + tig + 4];
            }
#pragma unroll
            for (int mi = 0; mi < 4; mi++)
#pragma unroll
                for (int ni = 0; ni < 4; ni++)
                    mma8(acc[mi][ni], a[mi], b[ni]);
        }
        __syncthreads();
    }

    // ---- epilogue ----
#pragma unroll
    for (int mi = 0; mi < 4; mi++) {
#pragma unroll
        for (int rr = 0; rr < 2; rr++) {
            int r = rowBase + wm + mi * 16 + gid + rr * 8;
            if (r >= M) continue;
#pragma unroll
            for (int ni = 0; ni < 4; ni++) {
                int c = colBase + wn + ni * 8 + 2 * tig;
                if (c >= HIDDEN) continue;   // c even, HIDDEN even -> c+1 ok
                float v0 = acc[mi][ni][rr * 2 + 0] + bias[c];
                float v1 = acc[mi][ni][rr * 2 + 1] + bias[c + 1];
                if (MODE == 2) {
                    const float* h0r = X + (size_t)r * HIDDEN + c;
                    v0 += h0r[0];
                    v1 += h0r[1];
                }
                v0 = fmaxf(v0, 0.f);
                v1 = fmaxf(v1, 0.f);
                *(float2*)(outp + (size_t)r * HIDDEN + c) = make_float2(v0, v1);
            }
        }
    }
}

// ---------------- launch ----------------------------------------------------
extern "C" void kernel_launch(void* const* d_in, const int* in_sizes, int n_in,
                              void* d_out, int out_size) {
    const float* x           = (const float*)d_in[0];
    const float* edge_attr   = (const float*)d_in[1];
    const float* edge_weight = (const float*)d_in[2];
    const float* W0          = (const float*)d_in[4];
    const float* b0          = (const float*)d_in[5];
    const float* W           = (const float*)d_in[6];
    const float* bvec        = (const float*)d_in[7];
    const int*   ei          = (const int*)d_in[8];

    int N = in_sizes[0] / NODE_D;
    int E = in_sizes[2];

    float* out_h  = (float*)d_out;
    float* out_h0 = out_h + (size_t)N * HIDDEN;

    zero_kernel<<<(N + 255) / 256, 256>>>(N);
    hist_kernel<<<(E + 255) / 256, 256>>>(ei, E);
    scan_kernel<<<1, 1024>>>(N);
    fill_kernel<<<(E + 255) / 256, 256>>>(ei, edge_weight, E);
    inc_kernel<<<((size_t)N * 32 + 255) / 256, 256>>>(edge_attr, N);

    dim3 gg((HIDDEN + 63) / 64, (N + 127) / 128);
    // gemm1: h0 -> out_h0 only (single copy; agg + gemm2 residual read it back)
    mma_gemm<1><<<gg, 128>>>(x, W0, b0, out_h0, N, KCAT);
    agg_kernel<<<((size_t)N * 32 + 255) / 256, 256>>>(out_h0, N);
    // gemm2: h = relu(h0 + agg @ W + b)
    mma_gemm<2><<<gg, 128>>>(out_h0, W, bvec, out_h, N, HIDDEN);
}